// round 3
// baseline (speedup 1.0000x reference)
#include <cuda_runtime.h>

// Guided filter, RADIUS=8, EPS=0.01, (8,3,1024,1024) fp32.
// Two fused kernels (horizontal box + vertical sliding box, trail rows
// recomputed from L2). 8 columns per thread to cut L1 window-overlap
// amplification; 128-thread blocks, 32-row segments for occupancy.

#define W     1024
#define Hh    1024
#define IMGS  24
#define HW    (Hh * W)
#define TOTAL (IMGS * HW)
#define RAD   8
#define EPSF  0.01f
#define SEGR  32
#define SEGS  (Hh / SEGR)
#define CPT   8               // columns per thread
#define TPB   (W / CPT)       // 128 threads cover a full row

__device__ __align__(16) float g_a[TOTAL];
__device__ __align__(16) float g_b[TOTAL];

// Accumulate (SGN=+1) or subtract (SGN=-1) the horizontal clipped box sums of
// one row of x,y (+ products) into the vertical running sums s0..s3 for the
// 8 columns col0..col0+7.  Window: cols [col0-8, col0+15], zero-padded.
template<int SGN>
__device__ __forceinline__ void accA(const float* __restrict__ xr,
                                     const float* __restrict__ yr,
                                     int col0, bool interior,
                                     float s0[CPT], float s1[CPT],
                                     float s2[CPT], float s3[CPT]) {
    float xv[24], yv[24];
    if (interior) {
        #pragma unroll
        for (int q = 0; q < 6; q++) {
            float4 vx = *(const float4*)(xr + col0 - RAD + 4 * q);
            float4 vy = *(const float4*)(yr + col0 - RAD + 4 * q);
            xv[4*q+0]=vx.x; xv[4*q+1]=vx.y; xv[4*q+2]=vx.z; xv[4*q+3]=vx.w;
            yv[4*q+0]=vy.x; yv[4*q+1]=vy.y; yv[4*q+2]=vy.z; yv[4*q+3]=vy.w;
        }
    } else {
        #pragma unroll
        for (int j = 0; j < 24; j++) {
            int c = col0 - RAD + j;
            bool ok = ((unsigned)c < (unsigned)W);
            xv[j] = ok ? xr[c] : 0.0f;
            yv[j] = ok ? yr[c] : 0.0f;
        }
    }
    float sx = 0.f, sy = 0.f, sxx = 0.f, sxy = 0.f;
    #pragma unroll
    for (int j = 0; j < 17; j++) {
        float a = xv[j], b = yv[j];
        sx += a; sy += b;
        sxx = fmaf(a, a, sxx);
        sxy = fmaf(a, b, sxy);
    }
    #pragma unroll
    for (int k = 0; k < CPT; k++) {
        if (k > 0) {
            float ao = xv[k-1], bo = yv[k-1];
            float an = xv[k+16], bn = yv[k+16];
            sx  += an - ao;
            sy  += bn - bo;
            sxx += an*an - ao*ao;
            sxy += an*bn - ao*bo;
        }
        if (SGN > 0) { s0[k] += sx; s1[k] += sy; s2[k] += sxx; s3[k] += sxy; }
        else         { s0[k] -= sx; s1[k] -= sy; s2[k] -= sxx; s3[k] -= sxy; }
    }
}

template<int SGN>
__device__ __forceinline__ void accB(const float* __restrict__ ar,
                                     const float* __restrict__ br,
                                     int col0, bool interior,
                                     float sa[CPT], float sb[CPT]) {
    float av[24], bv[24];
    if (interior) {
        #pragma unroll
        for (int q = 0; q < 6; q++) {
            float4 va = *(const float4*)(ar + col0 - RAD + 4 * q);
            float4 vb = *(const float4*)(br + col0 - RAD + 4 * q);
            av[4*q+0]=va.x; av[4*q+1]=va.y; av[4*q+2]=va.z; av[4*q+3]=va.w;
            bv[4*q+0]=vb.x; bv[4*q+1]=vb.y; bv[4*q+2]=vb.z; bv[4*q+3]=vb.w;
        }
    } else {
        #pragma unroll
        for (int j = 0; j < 24; j++) {
            int c = col0 - RAD + j;
            bool ok = ((unsigned)c < (unsigned)W);
            av[j] = ok ? ar[c] : 0.0f;
            bv[j] = ok ? br[c] : 0.0f;
        }
    }
    float sx = 0.f, sy = 0.f;
    #pragma unroll
    for (int j = 0; j < 17; j++) { sx += av[j]; sy += bv[j]; }
    #pragma unroll
    for (int k = 0; k < CPT; k++) {
        if (k > 0) {
            sx += av[k+16] - av[k-1];
            sy += bv[k+16] - bv[k-1];
        }
        if (SGN > 0) { sa[k] += sx; sb[k] += sy; }
        else         { sa[k] -= sx; sb[k] -= sy; }
    }
}

// ---------------------------------------------------------------------------
// Stage A: x,y -> a,b.  One thread = 8 columns, marches SEGR rows.
// ---------------------------------------------------------------------------
__global__ void __launch_bounds__(TPB) kA(const float* __restrict__ x,
                                          const float* __restrict__ y) {
    int img  = blockIdx.y;
    int s    = blockIdx.x * SEGR;
    int col0 = threadIdx.x * CPT;
    const float* xb = x + img * HW;
    const float* yb = y + img * HW;
    bool interior = (col0 >= RAD) && (col0 + 15 < W);

    float s0[CPT], s1[CPT], s2[CPT], s3[CPT];
    #pragma unroll
    for (int j = 0; j < CPT; j++) { s0[j]=0.f; s1[j]=0.f; s2[j]=0.f; s3[j]=0.f; }

    for (int r = max(0, s - RAD); r <= s + RAD; r++)
        accA<+1>(xb + r * W, yb + r * W, col0, interior, s0, s1, s2, s3);

    float nxv[CPT];
    #pragma unroll
    for (int j = 0; j < CPT; j++) {
        int c = col0 + j;
        nxv[j] = (float)(min(W - 1, c + RAD) - max(0, c - RAD) + 1);
    }

    float* ga = g_a + img * HW;
    float* gb = g_b + img * HW;

    for (int o = s; o < s + SEGR; o++) {
        float ny = (float)(min(Hh - 1, o + RAD) - max(0, o - RAD) + 1);
        float ra[CPT], rb[CPT];
        #pragma unroll
        for (int j = 0; j < CPT; j++) {
            float invN = __frcp_rn(nxv[j] * ny);
            float mx = s0[j] * invN, my = s1[j] * invN;
            float varx = fmaf(-mx, mx, s2[j] * invN);
            float cov  = fmaf(-mx, my, s3[j] * invN);
            float a = __fdividef(cov, varx + EPSF);
            ra[j] = a;
            rb[j] = fmaf(-a, mx, my);
        }
        #pragma unroll
        for (int q = 0; q < 2; q++) {
            float4 av, bv;
            av.x = ra[4*q+0]; av.y = ra[4*q+1]; av.z = ra[4*q+2]; av.w = ra[4*q+3];
            bv.x = rb[4*q+0]; bv.y = rb[4*q+1]; bv.z = rb[4*q+2]; bv.w = rb[4*q+3];
            *(float4*)(ga + o * W + col0 + 4*q) = av;
            *(float4*)(gb + o * W + col0 + 4*q) = bv;
        }

        int lead = o + RAD + 1, trail = o - RAD;
        if (lead < Hh)
            accA<+1>(xb + lead * W, yb + lead * W, col0, interior, s0, s1, s2, s3);
        if (trail >= 0)
            accA<-1>(xb + trail * W, yb + trail * W, col0, interior, s0, s1, s2, s3);
    }
}

// ---------------------------------------------------------------------------
// Stage B: a,b,x -> out.
// ---------------------------------------------------------------------------
__global__ void __launch_bounds__(TPB) kB(const float* __restrict__ x,
                                          float* __restrict__ out) {
    int img  = blockIdx.y;
    int s    = blockIdx.x * SEGR;
    int col0 = threadIdx.x * CPT;
    const float* ab = g_a + img * HW;
    const float* bb = g_b + img * HW;
    const float* xb = x + img * HW;
    float* ob = out + img * HW;
    bool interior = (col0 >= RAD) && (col0 + 15 < W);

    float sa[CPT], sb[CPT];
    #pragma unroll
    for (int j = 0; j < CPT; j++) { sa[j]=0.f; sb[j]=0.f; }

    for (int r = max(0, s - RAD); r <= s + RAD; r++)
        accB<+1>(ab + r * W, bb + r * W, col0, interior, sa, sb);

    float nxv[CPT];
    #pragma unroll
    for (int j = 0; j < CPT; j++) {
        int c = col0 + j;
        nxv[j] = (float)(min(W - 1, c + RAD) - max(0, c - RAD) + 1);
    }

    for (int o = s; o < s + SEGR; o++) {
        float ny = (float)(min(Hh - 1, o + RAD) - max(0, o - RAD) + 1);
        #pragma unroll
        for (int q = 0; q < 2; q++) {
            float4 xv = *(const float4*)(xb + o * W + col0 + 4*q);
            float xs[4] = {xv.x, xv.y, xv.z, xv.w};
            float4 ov;
            float os[4];
            #pragma unroll
            for (int j = 0; j < 4; j++) {
                int k = 4*q + j;
                float invN = __frcp_rn(nxv[k] * ny);
                os[j] = fmaf(sa[k] * invN, xs[j], sb[k] * invN);
            }
            ov.x = os[0]; ov.y = os[1]; ov.z = os[2]; ov.w = os[3];
            *(float4*)(ob + o * W + col0 + 4*q) = ov;
        }

        int lead = o + RAD + 1, trail = o - RAD;
        if (lead < Hh)
            accB<+1>(ab + lead * W, bb + lead * W, col0, interior, sa, sb);
        if (trail >= 0)
            accB<-1>(ab + trail * W, bb + trail * W, col0, interior, sa, sb);
    }
}

extern "C" void kernel_launch(void* const* d_in, const int* in_sizes, int n_in,
                              void* d_out, int out_size) {
    const float* x = (const float*)d_in[0];
    const float* y = (const float*)d_in[1];
    float* out = (float*)d_out;

    dim3 grid(SEGS, IMGS);
    kA<<<grid, TPB>>>(x, y);
    kB<<<grid, TPB>>>(x, out);
}